// round 16
// baseline (speedup 1.0000x reference)
#include <cuda_runtime.h>
#include <cstdint>

#define T_STEPS 1024
#define NB 8192
#define NP 6
#define B1 8                         // batch (steps per pipeline stage)
#define NBT1 (T_STEPS / B1)          // 128 batches
#define STAGES 8                     // cp.async ring depth per warp
#define SMEM_BYTES 122880            // 120 KB: forces 1 block per SM
#define RING_WARP_FLOATS (STAGES * 3 * B1 * 32)   // 6144 floats = 24 KB/warp (x4 = 96 KB)

struct Params {
    float Qmax, Df, Tmax, Tmin, Smax, invSmax, posf_l2, c0;
};

__device__ __forceinline__ float ex2_approx(float x)
{
    float y;
    asm("ex2.approx.ftz.f32 %0, %1;" : "=f"(y) : "f"(x));
    return y;
}

__device__ __forceinline__ Params load_params(const float* __restrict__ sp, int b)
{
    const float lo[NP] = {0.0f, 100.0f, 10.0f, 0.0f, 0.0f, -3.0f};
    const float hi[NP] = {0.1f, 1500.0f, 50.0f, 5.0f, 3.0f, 0.0f};
    float prm[NP];
#pragma unroll
    for (int i = 0; i < NP; i++) {
        float x = sp[b * NP + i];
        float s = 1.0f / (1.0f + __expf(-x));
        prm[i] = lo[i] + (hi[i] - lo[i]) * s;
    }
    Params q;
    q.Smax = prm[1]; q.Qmax = prm[2]; q.Df = prm[3];
    q.Tmax = prm[4]; q.Tmin = prm[5];
    q.invSmax = 1.0f / prm[1];
    const float negf_l2 = -prm[0] * 1.4426950408889634f;   // -f*log2(e)
    q.posf_l2 = -negf_l2;
    q.c0 = negf_l2 * prm[1];                                // -f*log2(e)*Smax
    return q;
}

__device__ __forceinline__ void cpasync16(unsigned int dst_smem, const float* src)
{
    asm volatile("cp.async.cg.shared.global [%0], [%1], 16;"
                 :: "r"(dst_smem), "l"(src));
}
__device__ __forceinline__ void cp_commit()
{
    asm volatile("cp.async.commit_group;" ::: "memory");
}
template <int N>
__device__ __forceinline__ void cp_wait()
{
    asm volatile("cp.async.wait_group %0;" :: "n"(N) : "memory");
}

// Duplicate-chain direct-store scan, FLUX-split stores:
//   4 warps/SM, one per SMSP. Warp w computes basin half (w&1); the pair
//   (w>>1) determines WHICH fluxes it stores every step:
//     warps 0,1 -> fluxes 0..3 (snowfall, rainfall, melt, evap)
//     warps 2,3 -> fluxes 4..7 (baseflow, surfaceflow, d_snow, d_soil)
//   Chains are bit-identical; store stream is uniform (4 STG/step/warp),
//   no bursts, no branches, zero inter-warp synchronization.
__global__ void __launch_bounds__(128, 1)
hydro_dupf(const float* __restrict__ prcp,
           const float* __restrict__ temp,
           const float* __restrict__ pet,
           const float* __restrict__ sp,
           float* __restrict__ out)
{
    extern __shared__ float smem_dyn[];

    const int tid   = threadIdx.x;
    const int w     = tid >> 5;
    const int lane  = tid & 31;
    const int g     = w & 1;            // basin half within block's 64 basins
    const int fh    = w >> 1;           // flux half this warp stores (0 or 1)
    const int bb    = blockIdx.x * 64;
    const int b     = bb + g * 32 + lane;
    const int wbase = bb + g * 32;
    const Params q  = load_params(sp, b);

    float* wring = smem_dyn + w * RING_WARP_FLOATS;

    const float* vp0 = prcp + wbase;
    const float* vp1 = temp + wbase;
    const float* vp2 = pet  + wbase;

    // cooperative vectorized fill: 24 rows of 128B per batch -> 192 x 16B
    // lane l handles seg = l&7, rows (l>>3)+4j, j=0..5
    const int seg = lane & 7;
    const int r0  = lane >> 3;
    auto issue = [&](int batch, int s) {
        const int bc = (batch < NBT1) ? batch : NBT1 - 1;
        const size_t tbase = (size_t)bc * B1 * NB;
#pragma unroll
        for (int j = 0; j < 6; j++) {
            const int row = r0 + 4 * j;            // 0..23
            const int a   = row >> 3;              // forcing array
            const int i   = row & 7;               // step within batch
            const float* src = (a == 0 ? vp0 : (a == 1 ? vp1 : vp2))
                             + tbase + (size_t)i * NB + seg * 4;
            unsigned int dst = (unsigned int)__cvta_generic_to_shared(
                wring + ((s * 3 + a) * B1 + i) * 32 + seg * 4);
            cpasync16(dst, src);
        }
        cp_commit();
    };

#pragma unroll
    for (int s = 0; s < STAGES - 1; s++)
        issue(s, s);

    float snow = 0.0f, soil = 0.0f;
    // warp stores rows [fh*4, fh*4+4) of each 8-row timestep group
    float* o = out + b + (size_t)fh * 4 * NB;

    for (int tb = 0; tb < NBT1; tb++) {
        issue(tb + STAGES - 1, (tb + STAGES - 1) % STAGES);
        cp_wait<STAGES - 1>();
        __syncwarp();

        const int s = tb % STAGES;
        const float* rs = wring + s * 3 * B1 * 32;

#pragma unroll
        for (int i = 0; i < B1; i++) {
            const float p  = rs[(0 * B1 + i) * 32 + lane];
            const float tm = rs[(1 * B1 + i) * 32 + lane];
            const float pe = rs[(2 * B1 + i) * 32 + lane];

            const float snowfall    = (tm < q.Tmin) ? p : 0.0f;
            const float rainfall    = p - snowfall;
            const float melt        = fminf(snow, q.Df * fmaxf(tm - q.Tmax, 0.0f));
            const float evap        = pe * fminf(soil * q.invSmax, 1.0f);
            const float baseflow    = q.Qmax *
                ex2_approx(fminf(fmaf(q.posf_l2, soil, q.c0), 0.0f));
            const float surfaceflow = fmaxf(soil - q.Smax, 0.0f);

            const float d_snow = snowfall - melt;
            const float d_soil = rainfall + melt - evap - baseflow - surfaceflow;

            snow = fmaxf(snow + d_snow, 1e-6f);
            soil = fmaxf(soil + d_soil, 1e-6f);

            if (fh == 0) {
                __stcs(o + 0 * NB, snowfall);
                __stcs(o + 1 * NB, rainfall);
                __stcs(o + 2 * NB, melt);
                __stcs(o + 3 * NB, evap);
            } else {
                __stcs(o + 0 * NB, baseflow);
                __stcs(o + 1 * NB, surfaceflow);
                __stcs(o + 2 * NB, d_snow);
                __stcs(o + 3 * NB, d_soil);
            }
            o += 8 * NB;
        }
    }
}

extern "C" void kernel_launch(void* const* d_in, const int* in_sizes, int n_in,
                              void* d_out, int out_size)
{
    const float* prcp = (const float*)d_in[0];
    const float* temp = (const float*)d_in[1];
    const float* pet  = (const float*)d_in[2];
    const float* sp   = (const float*)d_in[3];
    float* out = (float*)d_out;

    cudaFuncSetAttribute(hydro_dupf,
                         cudaFuncAttributeMaxDynamicSharedMemorySize, SMEM_BYTES);

    // 128 blocks x 128 threads: 1 block/SM (120 KB smem), 4 warps on 4 SMSPs.
    // Chains duplicated across flux-half pairs; each warp stores 4 fluxes/step.
    hydro_dupf<<<128, 128, SMEM_BYTES>>>(prcp, temp, pet, sp, out);
}